// round 15
// baseline (speedup 1.0000x reference)
#include <cuda_runtime.h>
#include <cuda_fp16.h>
#include <cstdint>
#include <cstddef>

#define T_STEPS 8192
#define F_DIM   1024
#define H_DIM   2048
#define G_DIM   (4 * H_DIM)
#define MAXB    256
#define NB      128            // persistent CTAs: 16 hidden units / 64 gate rows each
#define P64     0x7E7E7E7E7E7E7E7EULL   // fp16 NaN x4; finite h never matches
#define NW_REG  36             // weight uint4 per thread in registers
#define NW_SMEM 28             // weight uint4 per thread in SMEM

// ---------------------------------------------------------------------------
// Static device scratch (no cudaMalloc anywhere)
// ---------------------------------------------------------------------------
__device__ float                    g_XG[(size_t)T_STEPS * G_DIM];   // x-gates, 256 MB
__device__ __half                   g_Whf[(size_t)G_DIM * H_DIM];    // fp16 W_hh, 32 MB
__device__ __half                   g_Xh [(size_t)T_STEPS * F_DIM];  // fp16 input, 16 MB
__device__ __half                   g_Wih[(size_t)G_DIM * F_DIM];    // fp16 W_ih, 16 MB
__device__ unsigned long long       g_hx[NB][4][512];                // consumer-private h rings, 2 MB
__device__ float                    g_partial[(size_t)T_STEPS * MAXB];

// ---------------------------------------------------------------------------
// Helpers
// ---------------------------------------------------------------------------
__device__ __forceinline__ unsigned sptr(const void* p) {
    unsigned a;
    asm("{ .reg .u64 t; cvta.to.shared.u64 t, %1; cvt.u32.u64 %0, t; }"
        : "=r"(a) : "l"(p));
    return a;
}
__device__ __forceinline__ void cp16(unsigned s, const void* g) {
    asm volatile("cp.async.cg.shared.global [%0], [%1], 16;" :: "r"(s), "l"(g));
}
__device__ __forceinline__ __half2 u2h(unsigned x) {
    __half2 h; *reinterpret_cast<unsigned*>(&h) = x; return h;
}
__device__ __forceinline__ void mac4(uint4 w, uint4 h, __half2& acc) {
    acc = __hfma2(u2h(w.x), u2h(h.x), acc);
    acc = __hfma2(u2h(w.y), u2h(h.y), acc);
    acc = __hfma2(u2h(w.z), u2h(h.z), acc);
    acc = __hfma2(u2h(w.w), u2h(h.w), acc);
}
__device__ __forceinline__ float tanh_fast(float x) {
    float y; asm("tanh.approx.f32 %0, %1;" : "=f"(y) : "f"(x)); return y;
}
__device__ __forceinline__ float sig_fast(float x) {
    return 0.5f + 0.5f * tanh_fast(0.5f * x);
}
__device__ __forceinline__ unsigned long long ldrlx64(const unsigned long long* p) {
    unsigned long long v;
    asm volatile("ld.relaxed.gpu.global.u64 %0, [%1];" : "=l"(v) : "l"(p) : "memory");
    return v;
}
__device__ __forceinline__ void strlx64(unsigned long long* p, unsigned long long v) {
    asm volatile("st.relaxed.gpu.global.u64 [%0], %1;" :: "l"(p), "l"(v) : "memory");
}

// ---------------------------------------------------------------------------
// Kernel 0: init h rings (slots 0-2 poison, slot 3 = h(-1) = 0)
// ---------------------------------------------------------------------------
__global__ void init_hx() {
    int i = blockIdx.x * blockDim.x + threadIdx.x;
    const int tot = NB * 4 * 512;
    if (i >= tot) return;
    int slot = (i >> 9) & 3;
    reinterpret_cast<unsigned long long*>(g_hx)[i] = (slot == 3) ? 0ULL : P64;
}

// ---------------------------------------------------------------------------
// Kernel 1: fp32 -> fp16 conversion (X, W_ih, W_hh)
// ---------------------------------------------------------------------------
__global__ void conv_f2h(const float* __restrict__ S, __half* __restrict__ D, int n4) {
    int i = blockIdx.x * blockDim.x + threadIdx.x;
    if (i >= n4) return;
    float4 v = reinterpret_cast<const float4*>(S)[i];
    __half2* o = reinterpret_cast<__half2*>(D);
    o[i * 2 + 0] = __floats2half2_rn(v.x, v.y);
    o[i * 2 + 1] = __floats2half2_rn(v.z, v.w);
}

// ---------------------------------------------------------------------------
// Kernel 2: XG = X @ W_ih^T + b  via HMMA m16n8k16 (fp16 in, fp32 accum)
// ---------------------------------------------------------------------------
__global__ __launch_bounds__(256, 2) void gemm_xg_h(
    const float* __restrict__ bi, const float* __restrict__ bh)
{
    __shared__ __align__(16) __half As[2][128][40];
    __shared__ __align__(16) __half Ws[2][128][40];

    const int tid  = threadIdx.x;
    const int lane = tid & 31;
    const int wid  = tid >> 5;
    const int wm   = wid >> 2;
    const int wn   = wid & 3;
    const int bm   = blockIdx.y * 128;
    const int bn   = blockIdx.x * 128;
    const int fg   = lane >> 2;
    const int kq   = lane & 3;

    float c[4][4][4];
#pragma unroll
    for (int a = 0; a < 4; a++)
#pragma unroll
        for (int b = 0; b < 4; b++)
#pragma unroll
            for (int d = 0; d < 4; d++) c[a][b][d] = 0.f;

    float2 bias2[4];
#pragma unroll
    for (int nb = 0; nb < 4; nb++) {
        int col = bn + wn * 32 + nb * 8 + kq * 2;
        bias2[nb] = make_float2(bi[col] + bh[col], bi[col + 1] + bh[col + 1]);
    }

    const int lrow = tid >> 1, lq = tid & 1;
    const __half* gA = g_Xh  + (size_t)(bm + lrow) * F_DIM + lq * 16;
    const __half* gW = g_Wih + (size_t)(bn + lrow) * F_DIM + lq * 16;

    auto load_buf = [&](int buf, int k0) {
        unsigned da = sptr(&As[buf][lrow][lq * 16]);
        unsigned dw = sptr(&Ws[buf][lrow][lq * 16]);
        cp16(da,      gA + k0);
        cp16(da + 16, gA + k0 + 8);
        cp16(dw,      gW + k0);
        cp16(dw + 16, gW + k0 + 8);
    };

    load_buf(0, 0);
    asm volatile("cp.async.commit_group;" ::: "memory");
    asm volatile("cp.async.wait_group 0;" ::: "memory");
    __syncthreads();

    int buf = 0;
    for (int kt = 0; kt < F_DIM / 32; kt++) {
        if (kt + 1 < F_DIM / 32) {
            load_buf(buf ^ 1, (kt + 1) * 32);
            asm volatile("cp.async.commit_group;" ::: "memory");
        }
#pragma unroll
        for (int ks = 0; ks < 32; ks += 16) {
            unsigned bf[4][2];
#pragma unroll
            for (int nb = 0; nb < 4; nb++) {
                const __half* wp = &Ws[buf][wn * 32 + nb * 8 + fg][ks + kq * 2];
                bf[nb][0] = *reinterpret_cast<const unsigned*>(wp);
                bf[nb][1] = *reinterpret_cast<const unsigned*>(wp + 8);
            }
#pragma unroll
            for (int mb = 0; mb < 4; mb++) {
                const __half* ap = &As[buf][wm * 64 + mb * 16 + fg][ks + kq * 2];
                unsigned a0 = *reinterpret_cast<const unsigned*>(ap);
                unsigned a1 = *reinterpret_cast<const unsigned*>(ap + 8 * 40);
                unsigned a2 = *reinterpret_cast<const unsigned*>(ap + 8);
                unsigned a3 = *reinterpret_cast<const unsigned*>(ap + 8 * 40 + 8);
#pragma unroll
                for (int nb = 0; nb < 4; nb++) {
                    asm volatile(
                        "mma.sync.aligned.m16n8k16.row.col.f32.f16.f16.f32 "
                        "{%0,%1,%2,%3}, {%4,%5,%6,%7}, {%8,%9}, {%0,%1,%2,%3};"
                        : "+f"(c[mb][nb][0]), "+f"(c[mb][nb][1]),
                          "+f"(c[mb][nb][2]), "+f"(c[mb][nb][3])
                        : "r"(a0), "r"(a1), "r"(a2), "r"(a3),
                          "r"(bf[nb][0]), "r"(bf[nb][1]));
                }
            }
        }
        if (kt + 1 < F_DIM / 32)
            asm volatile("cp.async.wait_group 0;" ::: "memory");
        __syncthreads();
        buf ^= 1;
    }

#pragma unroll
    for (int mb = 0; mb < 4; mb++) {
        int row = bm + wm * 64 + mb * 16 + fg;
#pragma unroll
        for (int nb = 0; nb < 4; nb++) {
            int col = bn + wn * 32 + nb * 8 + kq * 2;
            float2 v0 = make_float2(c[mb][nb][0] + bias2[nb].x,
                                    c[mb][nb][1] + bias2[nb].y);
            float2 v1 = make_float2(c[mb][nb][2] + bias2[nb].x,
                                    c[mb][nb][3] + bias2[nb].y);
            *reinterpret_cast<float2*>(g_XG + (size_t)row * G_DIM + col)       = v0;
            *reinterpret_cast<float2*>(g_XG + (size_t)(row + 8) * G_DIM + col) = v1;
        }
    }
}

// ---------------------------------------------------------------------------
// Kernel 3: persistent LSTM recurrence, self-timed dataflow sync.
// Changes vs R13: all 8 warps compute activations redundantly (c in shared
// double buffer) and publish in parallel (4 STG/lane to 16 consumers/warp);
// weight split 36 reg / 28 smem; poison written 2 slots ahead (safe: producer
// at step u implies all CTAs completed u-1); no nanosleep in the poll.
// ---------------------------------------------------------------------------
__global__ __launch_bounds__(256, 1) void lstm_kernel(
    const float* __restrict__ Wout)
{
    extern __shared__ uint4 wsmT[];       // NW_SMEM x 256 uint4, lane-transposed
    __shared__ uint4  h_sm4[4 * 65];      // h segments, stride 65 (conflict-free)
    __shared__ float  gates_sm[64];
    __shared__ float  xg_sm[2][64];
    __shared__ float  c_sm[2][16];

    const int tid  = threadIdx.x;
    const int lane = tid & 31;
    const int wid  = tid >> 5;
    const int b    = blockIdx.x;
    const int base = b * 16;

    const int row = wid * 8 + (lane >> 2);
    const int seg = lane & 3;

    auto growm = [&](int m) -> size_t {
        return (size_t)(m >> 4) * H_DIM + base + (m & 15);
    };

    const uint4* wp = reinterpret_cast<const uint4*>(
        g_Whf + growm(row) * H_DIM + seg * 512);

    uint4 wreg[NW_REG];
#pragma unroll
    for (int i = 0; i < NW_REG; i++) wreg[i] = __ldg(wp + i);
    for (int i = 0; i < NW_SMEM; i++) wsmT[i * 256 + tid] = __ldg(wp + NW_REG + i);

    const float wout = (lane < 16) ? Wout[base + lane] : 0.f;

    // xg software pipeline: xg_sm[0] = xg(0); xgr = xg(1) in registers
    float xgr = 0.f;
    const int xm = (wid - 4) * 32 + lane;     // valid for wid 4,5
    if (wid == 4 || wid == 5) {
        xg_sm[0][xm] = __ldg(g_XG + growm(xm));
        xgr = __ldg(g_XG + (size_t)1 * G_DIM + growm(xm));
    }
    if (tid < 16) c_sm[0][tid] = 0.f;
    __syncthreads();

    for (int t = 0; t < T_STEPS; t++) {
        const int rs = (t + 3) & 3;       // read slot: h(t-1)
        const int ws = t & 3;             // write slot: h(t)
        const int ps = (t + 2) & 3;       // poison 2 slots ahead

        // ---- poll OWN 16B of OWN mailbox (relaxed spin; poison-validated) ----
        {
            const unsigned long long* hp = &g_hx[b][rs][tid * 2];
            unsigned long long a0 = ldrlx64(hp);
            unsigned long long a1 = ldrlx64(hp + 1);
            while (a0 == P64 || a1 == P64) {
                if (a0 == P64) a0 = ldrlx64(hp);
                if (a1 == P64) a1 = ldrlx64(hp + 1);
            }
            uint4 hv;
            hv.x = (uint32_t)a0; hv.y = (uint32_t)(a0 >> 32);
            hv.z = (uint32_t)a1; hv.w = (uint32_t)(a1 >> 32);
            h_sm4[(tid >> 6) * 65 + (tid & 63)] = hv;
        }
        __syncthreads();

        // ---- per-thread dot over its 512-k segment ----
        const uint4* hA = &h_sm4[seg * 65];
        float dot = 0.f;
        __half2 acc = __half2half2(__ushort_as_half(0));
#pragma unroll
        for (int i = 0; i < NW_REG; i += 4) {
            mac4(wreg[i],     hA[i],     acc);
            mac4(wreg[i + 1], hA[i + 1], acc);
            mac4(wreg[i + 2], hA[i + 2], acc);
            mac4(wreg[i + 3], hA[i + 3], acc);
            float2 f = __half22float2(acc);
            dot += f.x + f.y;
            acc = __half2half2(__ushort_as_half(0));
        }
#pragma unroll
        for (int i = 0; i < NW_SMEM; i += 4) {
            mac4(wsmT[i * 256 + tid],       hA[NW_REG + i],     acc);
            mac4(wsmT[(i + 1) * 256 + tid], hA[NW_REG + i + 1], acc);
            mac4(wsmT[(i + 2) * 256 + tid], hA[NW_REG + i + 2], acc);
            mac4(wsmT[(i + 3) * 256 + tid], hA[NW_REG + i + 3], acc);
            float2 f = __half22float2(acc);
            dot += f.x + f.y;
            acc = __half2half2(__ushort_as_half(0));
        }

        // ---- xg pipeline (warps 4,5): STS xg(t+1), LDG xg(t+2) ----
        if (wid == 4 || wid == 5) {
            if (t + 1 < T_STEPS) xg_sm[(t + 1) & 1][xm] = xgr;
            if (t + 2 < T_STEPS)
                xgr = __ldg(g_XG + (size_t)(t + 2) * G_DIM + growm(xm));
        }

        // ---- quad reduction ----
        dot += __shfl_xor_sync(0xffffffffu, dot, 1);
        dot += __shfl_xor_sync(0xffffffffu, dot, 2);
        if (seg == 0) gates_sm[row] = dot;
        __syncthreads();

        // ---- redundant activations (ALL warps) + parallel scatter-publish ----
        float hn = 0.f;
        if (lane < 16) {
            float iv = gates_sm[lane]      + xg_sm[t & 1][lane];
            float fv = gates_sm[16 + lane] + xg_sm[t & 1][16 + lane];
            float gv = gates_sm[32 + lane] + xg_sm[t & 1][32 + lane];
            float ov = gates_sm[48 + lane] + xg_sm[t & 1][48 + lane];
            float cn = sig_fast(fv) * c_sm[t & 1][lane] + sig_fast(iv) * tanh_fast(gv);
            hn = sig_fast(ov) * tanh_fast(cn);
            if (wid == 0) c_sm[(t + 1) & 1][lane] = cn;
        }
        // pack 16 h into 4 u64 words (word (lane&3) on every lane)
        {
            float hnb = __shfl_xor_sync(0xffffffffu, hn, 1);
            __half2 hp2 = __floats2half2_rn(hn, hnb);
            uint32_t w32  = *reinterpret_cast<uint32_t*>(&hp2);
            uint32_t w32b = __shfl_xor_sync(0xffffffffu, w32, 2);
            uint32_t lo = __shfl_sync(0xffffffffu, w32,  (lane & 3) * 4);
            uint32_t hi = __shfl_sync(0xffffffffu, w32b, (lane & 3) * 4);
            unsigned long long wv =
                (unsigned long long)lo | ((unsigned long long)hi << 32);
            // this lane stores words j0=(lane&1)*2 and j0+1 for its consumer
            unsigned long long wv0 =
                __shfl_sync(0xffffffffu, wv, (lane & 28) | ((lane & 1) << 1));
            unsigned long long wv1 =
                __shfl_sync(0xffffffffu, wv, (lane & 28) | ((lane & 1) << 1) | 1);
            const int c  = wid * 16 + (lane >> 1);   // 8 warps x 16 = 128 consumers
            const int wi = b * 4 + ((lane & 1) << 1);
            strlx64(&g_hx[c][ps][wi],     P64);
            strlx64(&g_hx[c][ps][wi + 1], P64);
            strlx64(&g_hx[c][ws][wi],     wv0);
            strlx64(&g_hx[c][ws][wi + 1], wv1);
        }

        // ---- output partial (warp 7, off the publish path) ----
        if (wid == 7) {
            float pv = hn * wout;
#pragma unroll
            for (int o = 16; o; o >>= 1) pv += __shfl_xor_sync(0xffffffffu, pv, o);
            if (lane == 0) g_partial[(size_t)t * MAXB + b] = pv;
        }
        // no trailing barrier: next iteration's poll is the sync
    }
}

// ---------------------------------------------------------------------------
// Kernel 4: out[t] = b_out + sum_b partial[t][b]  (fixed order, deterministic)
// ---------------------------------------------------------------------------
__global__ void reduce_out(const float* __restrict__ bo, float* __restrict__ out) {
    int t = blockIdx.x * blockDim.x + threadIdx.x;
    if (t >= T_STEPS) return;
    float s = bo[0];
    const float* p = g_partial + (size_t)t * MAXB;
    for (int b = 0; b < NB; b++) s += p[b];
    out[t] = s;
}

// ---------------------------------------------------------------------------
// Host launcher (graph-capturable: kernels only)
// ---------------------------------------------------------------------------
extern "C" void kernel_launch(void* const* d_in, const int* in_sizes, int n_in,
                              void* d_out, int out_size)
{
    const float* input = (const float*)d_in[0];   // [T, 1, F]
    const float* W_ih  = (const float*)d_in[1];   // [4H, F]
    const float* W_hh  = (const float*)d_in[2];   // [4H, H]
    const float* b_ih  = (const float*)d_in[3];
    const float* b_hh  = (const float*)d_in[4];
    const float* W_out = (const float*)d_in[5];   // [1, H]
    const float* b_out = (const float*)d_in[6];
    float* out = (float*)d_out;                   // [T, 1, 1]

    const size_t smem = (size_t)NW_SMEM * 256 * sizeof(uint4);   // 114688 B
    cudaFuncSetAttribute(lstm_kernel, cudaFuncAttributeMaxDynamicSharedMemorySize,
                         (int)smem);

    init_hx<<<(NB * 4 * 512 + 255) / 256, 256>>>();

    __half* xh = nullptr;  cudaGetSymbolAddress((void**)&xh,  g_Xh);
    __half* wih = nullptr; cudaGetSymbolAddress((void**)&wih, g_Wih);
    __half* whf = nullptr; cudaGetSymbolAddress((void**)&whf, g_Whf);

    conv_f2h<<<(T_STEPS * F_DIM / 4 + 255) / 256, 256>>>(input, xh,
                                                         T_STEPS * F_DIM / 4);
    conv_f2h<<<(G_DIM * F_DIM / 4 + 255) / 256, 256>>>(W_ih, wih,
                                                       G_DIM * F_DIM / 4);
    conv_f2h<<<(G_DIM * H_DIM / 4 + 255) / 256, 256>>>(W_hh, whf,
                                                       G_DIM * H_DIM / 4);

    dim3 ggrid(G_DIM / 128, T_STEPS / 128);
    gemm_xg_h<<<ggrid, 256>>>(b_ih, b_hh);

    lstm_kernel<<<NB, 256, smem>>>(W_out);

    reduce_out<<<(T_STEPS + 255) / 256, 256>>>(b_out, out);
}

// round 16
// speedup vs baseline: 1.2678x; 1.2678x over previous
#include <cuda_runtime.h>
#include <cuda_fp16.h>
#include <cstdint>
#include <cstddef>

#define T_STEPS 8192
#define F_DIM   1024
#define H_DIM   2048
#define G_DIM   (4 * H_DIM)
#define MAXB    256
#define NB      128            // persistent CTAs: 16 hidden units / 64 gate rows each
#define P64     0x7E7E7E7E7E7E7E7EULL   // fp16 NaN x4; finite h never matches

// ---------------------------------------------------------------------------
// Static device scratch (no cudaMalloc anywhere)
// ---------------------------------------------------------------------------
__device__ float                    g_XG[(size_t)T_STEPS * G_DIM];   // x-gates, 256 MB
__device__ __half                   g_Whf[(size_t)G_DIM * H_DIM];    // fp16 W_hh, 32 MB
__device__ __half                   g_Xh [(size_t)T_STEPS * F_DIM];  // fp16 input, 16 MB
__device__ __half                   g_Wih[(size_t)G_DIM * F_DIM];    // fp16 W_ih, 16 MB
__device__ unsigned long long       g_hx[NB][4][512];                // consumer-private h rings, 2 MB
__device__ float                    g_partial[(size_t)T_STEPS * MAXB];

// ---------------------------------------------------------------------------
// Helpers
// ---------------------------------------------------------------------------
__device__ __forceinline__ unsigned sptr(const void* p) {
    unsigned a;
    asm("{ .reg .u64 t; cvta.to.shared.u64 t, %1; cvt.u32.u64 %0, t; }"
        : "=r"(a) : "l"(p));
    return a;
}
__device__ __forceinline__ void cp16(unsigned s, const void* g) {
    asm volatile("cp.async.cg.shared.global [%0], [%1], 16;" :: "r"(s), "l"(g));
}
__device__ __forceinline__ __half2 u2h(unsigned x) {
    __half2 h; *reinterpret_cast<unsigned*>(&h) = x; return h;
}
__device__ __forceinline__ void mac4(uint4 w, uint4 h, __half2& acc) {
    acc = __hfma2(u2h(w.x), u2h(h.x), acc);
    acc = __hfma2(u2h(w.y), u2h(h.y), acc);
    acc = __hfma2(u2h(w.z), u2h(h.z), acc);
    acc = __hfma2(u2h(w.w), u2h(h.w), acc);
}
__device__ __forceinline__ float tanh_fast(float x) {
    float y; asm("tanh.approx.f32 %0, %1;" : "=f"(y) : "f"(x)); return y;
}
__device__ __forceinline__ float sig_fast(float x) {
    return 0.5f + 0.5f * tanh_fast(0.5f * x);
}
__device__ __forceinline__ unsigned long long ldrlx64(const unsigned long long* p) {
    unsigned long long v;
    asm volatile("ld.relaxed.gpu.global.u64 %0, [%1];" : "=l"(v) : "l"(p) : "memory");
    return v;
}
__device__ __forceinline__ void strlx64(unsigned long long* p, unsigned long long v) {
    asm volatile("st.relaxed.gpu.global.u64 [%0], %1;" :: "l"(p), "l"(v) : "memory");
}

// ---------------------------------------------------------------------------
// Kernel 0: init h rings (slots 0-2 poison, slot 3 = h(-1) = 0)
// ---------------------------------------------------------------------------
__global__ void init_hx() {
    int i = blockIdx.x * blockDim.x + threadIdx.x;
    const int tot = NB * 4 * 512;
    if (i >= tot) return;
    int slot = (i >> 9) & 3;
    reinterpret_cast<unsigned long long*>(g_hx)[i] = (slot == 3) ? 0ULL : P64;
}

// ---------------------------------------------------------------------------
// Kernel 1: fp32 -> fp16 conversion (X, W_ih, W_hh)
// ---------------------------------------------------------------------------
__global__ void conv_f2h(const float* __restrict__ S, __half* __restrict__ D, int n4) {
    int i = blockIdx.x * blockDim.x + threadIdx.x;
    if (i >= n4) return;
    float4 v = reinterpret_cast<const float4*>(S)[i];
    __half2* o = reinterpret_cast<__half2*>(D);
    o[i * 2 + 0] = __floats2half2_rn(v.x, v.y);
    o[i * 2 + 1] = __floats2half2_rn(v.z, v.w);
}

// ---------------------------------------------------------------------------
// Kernel 2: XG = X @ W_ih^T + b  via HMMA m16n8k16 (fp16 in, fp32 accum)
// ---------------------------------------------------------------------------
__global__ __launch_bounds__(256, 2) void gemm_xg_h(
    const float* __restrict__ bi, const float* __restrict__ bh)
{
    __shared__ __align__(16) __half As[2][128][40];
    __shared__ __align__(16) __half Ws[2][128][40];

    const int tid  = threadIdx.x;
    const int lane = tid & 31;
    const int wid  = tid >> 5;
    const int wm   = wid >> 2;
    const int wn   = wid & 3;
    const int bm   = blockIdx.y * 128;
    const int bn   = blockIdx.x * 128;
    const int fg   = lane >> 2;
    const int kq   = lane & 3;

    float c[4][4][4];
#pragma unroll
    for (int a = 0; a < 4; a++)
#pragma unroll
        for (int b = 0; b < 4; b++)
#pragma unroll
            for (int d = 0; d < 4; d++) c[a][b][d] = 0.f;

    float2 bias2[4];
#pragma unroll
    for (int nb = 0; nb < 4; nb++) {
        int col = bn + wn * 32 + nb * 8 + kq * 2;
        bias2[nb] = make_float2(bi[col] + bh[col], bi[col + 1] + bh[col + 1]);
    }

    const int lrow = tid >> 1, lq = tid & 1;
    const __half* gA = g_Xh  + (size_t)(bm + lrow) * F_DIM + lq * 16;
    const __half* gW = g_Wih + (size_t)(bn + lrow) * F_DIM + lq * 16;

    auto load_buf = [&](int buf, int k0) {
        unsigned da = sptr(&As[buf][lrow][lq * 16]);
        unsigned dw = sptr(&Ws[buf][lrow][lq * 16]);
        cp16(da,      gA + k0);
        cp16(da + 16, gA + k0 + 8);
        cp16(dw,      gW + k0);
        cp16(dw + 16, gW + k0 + 8);
    };

    load_buf(0, 0);
    asm volatile("cp.async.commit_group;" ::: "memory");
    asm volatile("cp.async.wait_group 0;" ::: "memory");
    __syncthreads();

    int buf = 0;
    for (int kt = 0; kt < F_DIM / 32; kt++) {
        if (kt + 1 < F_DIM / 32) {
            load_buf(buf ^ 1, (kt + 1) * 32);
            asm volatile("cp.async.commit_group;" ::: "memory");
        }
#pragma unroll
        for (int ks = 0; ks < 32; ks += 16) {
            unsigned bf[4][2];
#pragma unroll
            for (int nb = 0; nb < 4; nb++) {
                const __half* wp = &Ws[buf][wn * 32 + nb * 8 + fg][ks + kq * 2];
                bf[nb][0] = *reinterpret_cast<const unsigned*>(wp);
                bf[nb][1] = *reinterpret_cast<const unsigned*>(wp + 8);
            }
#pragma unroll
            for (int mb = 0; mb < 4; mb++) {
                const __half* ap = &As[buf][wm * 64 + mb * 16 + fg][ks + kq * 2];
                unsigned a0 = *reinterpret_cast<const unsigned*>(ap);
                unsigned a1 = *reinterpret_cast<const unsigned*>(ap + 8 * 40);
                unsigned a2 = *reinterpret_cast<const unsigned*>(ap + 8);
                unsigned a3 = *reinterpret_cast<const unsigned*>(ap + 8 * 40 + 8);
#pragma unroll
                for (int nb = 0; nb < 4; nb++) {
                    asm volatile(
                        "mma.sync.aligned.m16n8k16.row.col.f32.f16.f16.f32 "
                        "{%0,%1,%2,%3}, {%4,%5,%6,%7}, {%8,%9}, {%0,%1,%2,%3};"
                        : "+f"(c[mb][nb][0]), "+f"(c[mb][nb][1]),
                          "+f"(c[mb][nb][2]), "+f"(c[mb][nb][3])
                        : "r"(a0), "r"(a1), "r"(a2), "r"(a3),
                          "r"(bf[nb][0]), "r"(bf[nb][1]));
                }
            }
        }
        if (kt + 1 < F_DIM / 32)
            asm volatile("cp.async.wait_group 0;" ::: "memory");
        __syncthreads();
        buf ^= 1;
    }

#pragma unroll
    for (int mb = 0; mb < 4; mb++) {
        int row = bm + wm * 64 + mb * 16 + fg;
#pragma unroll
        for (int nb = 0; nb < 4; nb++) {
            int col = bn + wn * 32 + nb * 8 + kq * 2;
            float2 v0 = make_float2(c[mb][nb][0] + bias2[nb].x,
                                    c[mb][nb][1] + bias2[nb].y);
            float2 v1 = make_float2(c[mb][nb][2] + bias2[nb].x,
                                    c[mb][nb][3] + bias2[nb].y);
            *reinterpret_cast<float2*>(g_XG + (size_t)row * G_DIM + col)       = v0;
            *reinterpret_cast<float2*>(g_XG + (size_t)(row + 8) * G_DIM + col) = v1;
        }
    }
}

// ---------------------------------------------------------------------------
// Kernel 3: persistent LSTM recurrence, self-timed dataflow sync (R13) with
// h-reuse task shape: warp w owns rows [8w,8w+8); lane l owns k-chunk
// [64l,64l+64). h chunk loaded ONCE into 8 uint4 registers and reused across
// 8 rows (h crossbar traffic /8). Weights rows 0-3 in registers, rows 4-7 in
// lane-transposed SMEM. Row dots reduced by a 5-level butterfly (8 trees).
// ---------------------------------------------------------------------------
__global__ __launch_bounds__(256, 1) void lstm_kernel(
    const float* __restrict__ Wout)
{
    extern __shared__ uint4 wsmT[];       // 32 x 256 uint4 = 128 KB, lane-transposed
    __shared__ uint4  h_sm4[256];         // h staged; loc s holds word ((s&31)<<3)|(s>>5)
    __shared__ float  gates_sm[64];
    __shared__ float  xg_sm[2][64];

    const int tid  = threadIdx.x;
    const int lane = tid & 31;
    const int wid  = tid >> 5;
    const int b    = blockIdx.x;
    const int base = b * 16;

    auto growm = [&](int m) -> size_t {
        return (size_t)(m >> 4) * H_DIM + base + (m & 15);
    };

    // ---- weights: rows 8w..8w+3 -> registers, rows 8w+4..8w+7 -> SMEM ----
    uint4 wreg[32];
#pragma unroll
    for (int m = 0; m < 4; m++) {
        const uint4* rp = reinterpret_cast<const uint4*>(
            g_Whf + growm(wid * 8 + m) * H_DIM);
#pragma unroll
        for (int j = 0; j < 8; j++) wreg[m * 8 + j] = __ldg(rp + lane * 8 + j);
    }
    for (int m = 4; m < 8; m++) {
        const uint4* rp = reinterpret_cast<const uint4*>(
            g_Whf + growm(wid * 8 + m) * H_DIM);
        for (int j = 0; j < 8; j++)
            wsmT[((m - 4) * 8 + j) * 256 + tid] = __ldg(rp + lane * 8 + j);
    }

    float creg = 0.f;
    const float wout = (wid == 0 && lane < 16) ? Wout[base + lane] : 0.f;

    // mailbox word this thread polls: the one it must stage at h_sm4[tid]
    const int hw = ((tid & 31) << 3) | (tid >> 5);

    // xg software pipeline: xg_sm[0] = xg(0); xgr = xg(1) in registers
    float xgr = 0.f;
    const int xm = (wid - 4) * 32 + lane;     // valid for wid 4,5
    if (wid == 4 || wid == 5) {
        xg_sm[0][xm] = __ldg(g_XG + growm(xm));
        xgr = __ldg(g_XG + (size_t)1 * G_DIM + growm(xm));
    }
    __syncthreads();

    for (int t = 0; t < T_STEPS; t++) {
        const int rs = (t + 3) & 3;       // read slot: h(t-1)
        const int ws = t & 3;             // write slot: h(t)
        const int ps = (t + 1) & 3;       // poison-ahead slot

        // ---- poll OWN 16B of OWN mailbox (relaxed; poison-validated) ----
        {
            const unsigned long long* hp = &g_hx[b][rs][hw * 2];
            unsigned long long a0 = ldrlx64(hp);
            unsigned long long a1 = ldrlx64(hp + 1);
            while (a0 == P64 || a1 == P64) {
                __nanosleep(20);
                if (a0 == P64) a0 = ldrlx64(hp);
                if (a1 == P64) a1 = ldrlx64(hp + 1);
            }
            uint4 hv;
            hv.x = (uint32_t)a0; hv.y = (uint32_t)(a0 >> 32);
            hv.z = (uint32_t)a1; hv.w = (uint32_t)(a1 >> 32);
            h_sm4[tid] = hv;              // conflict-free (consecutive)
        }
        __syncthreads();

        // ---- h chunk into registers: 8 uint4, conflict-free reads ----
        uint4 hreg[8];
#pragma unroll
        for (int j = 0; j < 8; j++) hreg[j] = h_sm4[j * 32 + lane];

        // ---- 8 row-dots, h reused from registers ----
        float dots[8];
#pragma unroll
        for (int m = 0; m < 4; m++) {
            __half2 a0 = __half2half2(__ushort_as_half(0));
            __half2 a1 = __half2half2(__ushort_as_half(0));
            mac4(wreg[m * 8 + 0], hreg[0], a0);
            mac4(wreg[m * 8 + 1], hreg[1], a1);
            mac4(wreg[m * 8 + 2], hreg[2], a0);
            mac4(wreg[m * 8 + 3], hreg[3], a1);
            float2 f0 = __half22float2(a0);
            float2 f1 = __half22float2(a1);
            float d = (f0.x + f0.y) + (f1.x + f1.y);
            a0 = __half2half2(__ushort_as_half(0));
            a1 = __half2half2(__ushort_as_half(0));
            mac4(wreg[m * 8 + 4], hreg[4], a0);
            mac4(wreg[m * 8 + 5], hreg[5], a1);
            mac4(wreg[m * 8 + 6], hreg[6], a0);
            mac4(wreg[m * 8 + 7], hreg[7], a1);
            f0 = __half22float2(a0);
            f1 = __half22float2(a1);
            dots[m] = d + (f0.x + f0.y) + (f1.x + f1.y);
        }
#pragma unroll
        for (int m = 4; m < 8; m++) {
            const uint4* wr = wsmT + ((m - 4) * 8) * 256 + tid;
            __half2 a0 = __half2half2(__ushort_as_half(0));
            __half2 a1 = __half2half2(__ushort_as_half(0));
            mac4(wr[0 * 256], hreg[0], a0);
            mac4(wr[1 * 256], hreg[1], a1);
            mac4(wr[2 * 256], hreg[2], a0);
            mac4(wr[3 * 256], hreg[3], a1);
            float2 f0 = __half22float2(a0);
            float2 f1 = __half22float2(a1);
            float d = (f0.x + f0.y) + (f1.x + f1.y);
            a0 = __half2half2(__ushort_as_half(0));
            a1 = __half2half2(__ushort_as_half(0));
            mac4(wr[4 * 256], hreg[4], a0);
            mac4(wr[5 * 256], hreg[5], a1);
            mac4(wr[6 * 256], hreg[6], a0);
            mac4(wr[7 * 256], hreg[7], a1);
            f0 = __half22float2(a0);
            f1 = __half22float2(a1);
            dots[m] = d + (f0.x + f0.y) + (f1.x + f1.y);
        }

        // ---- xg pipeline (warps 4,5): STS xg(t+1), LDG xg(t+2) ----
        if (wid == 4 || wid == 5) {
            if (t + 1 < T_STEPS) xg_sm[(t + 1) & 1][xm] = xgr;
            if (t + 2 < T_STEPS)
                xgr = __ldg(g_XG + (size_t)(t + 2) * G_DIM + growm(xm));
        }

        // ---- butterfly reduction: 8 interleaved trees, 5 levels ----
#pragma unroll
        for (int o = 16; o; o >>= 1) {
#pragma unroll
            for (int m = 0; m < 8; m++)
                dots[m] += __shfl_xor_sync(0xffffffffu, dots[m], o);
        }
        if (lane == 0) {
#pragma unroll
            for (int m = 0; m < 8; m++) gates_sm[wid * 8 + m] = dots[m];
        }
        __syncthreads();

        // ---- activations + scatter-publish (warp 0); others loop to poll ----
        if (wid == 0) {
            float hn = 0.f;
            if (lane < 16) {
                float iv = gates_sm[lane]      + xg_sm[t & 1][lane];
                float fv = gates_sm[16 + lane] + xg_sm[t & 1][16 + lane];
                float gv = gates_sm[32 + lane] + xg_sm[t & 1][32 + lane];
                float ov = gates_sm[48 + lane] + xg_sm[t & 1][48 + lane];
                float cn = sig_fast(fv) * creg + sig_fast(iv) * tanh_fast(gv);
                hn = sig_fast(ov) * tanh_fast(cn);
                creg = cn;
            }
            // pack 16 h values into 4 u64 words, replicated to all lanes
            float hnb = __shfl_xor_sync(0xffffffffu, hn, 1);
            __half2 hp2 = __floats2half2_rn(hn, hnb);
            uint32_t w32  = *reinterpret_cast<uint32_t*>(&hp2);
            uint32_t w32b = __shfl_xor_sync(0xffffffffu, w32, 2);
            uint32_t lo = __shfl_sync(0xffffffffu, w32,  (lane & 3) * 4);
            uint32_t hi = __shfl_sync(0xffffffffu, w32b, (lane & 3) * 4);
            unsigned long long wv =
                (unsigned long long)lo | ((unsigned long long)hi << 32);

            const int widx = b * 4 + (lane & 3);
            const int cg   = lane >> 2;
#pragma unroll
            for (int i = 0; i < 16; i++) {
                int c = cg + 8 * i;
                strlx64(&g_hx[c][ps][widx], P64);   // poison ahead (relaxed)
                strlx64(&g_hx[c][ws][widx], wv);    // data (relaxed, poison-validated)
            }

            // output partial (after publish; off other CTAs' critical path)
            float pv = hn * wout;
#pragma unroll
            for (int o = 16; o; o >>= 1) pv += __shfl_xor_sync(0xffffffffu, pv, o);
            if (lane == 0) g_partial[(size_t)t * MAXB + b] = pv;
        }
        // no trailing barrier: next iteration's poll is the sync
    }
}

// ---------------------------------------------------------------------------
// Kernel 4: out[t] = b_out + sum_b partial[t][b]  (fixed order, deterministic)
// ---------------------------------------------------------------------------
__global__ void reduce_out(const float* __restrict__ bo, float* __restrict__ out) {
    int t = blockIdx.x * blockDim.x + threadIdx.x;
    if (t >= T_STEPS) return;
    float s = bo[0];
    const float* p = g_partial + (size_t)t * MAXB;
    for (int b = 0; b < NB; b++) s += p[b];
    out[t] = s;
}

// ---------------------------------------------------------------------------
// Host launcher (graph-capturable: kernels only)
// ---------------------------------------------------------------------------
extern "C" void kernel_launch(void* const* d_in, const int* in_sizes, int n_in,
                              void* d_out, int out_size)
{
    const float* input = (const float*)d_in[0];   // [T, 1, F]
    const float* W_ih  = (const float*)d_in[1];   // [4H, F]
    const float* W_hh  = (const float*)d_in[2];   // [4H, H]
    const float* b_ih  = (const float*)d_in[3];
    const float* b_hh  = (const float*)d_in[4];
    const float* W_out = (const float*)d_in[5];   // [1, H]
    const float* b_out = (const float*)d_in[6];
    float* out = (float*)d_out;                   // [T, 1, 1]

    const size_t smem = (size_t)32 * 256 * sizeof(uint4);   // 131072 B
    cudaFuncSetAttribute(lstm_kernel, cudaFuncAttributeMaxDynamicSharedMemorySize,
                         (int)smem);

    init_hx<<<(NB * 4 * 512 + 255) / 256, 256>>>();

    __half* xh = nullptr;  cudaGetSymbolAddress((void**)&xh,  g_Xh);
    __half* wih = nullptr; cudaGetSymbolAddress((void**)&wih, g_Wih);
    __half* whf = nullptr; cudaGetSymbolAddress((void**)&whf, g_Whf);

    conv_f2h<<<(T_STEPS * F_DIM / 4 + 255) / 256, 256>>>(input, xh,
                                                         T_STEPS * F_DIM / 4);
    conv_f2h<<<(G_DIM * F_DIM / 4 + 255) / 256, 256>>>(W_ih, wih,
                                                       G_DIM * F_DIM / 4);
    conv_f2h<<<(G_DIM * H_DIM / 4 + 255) / 256, 256>>>(W_hh, whf,
                                                       G_DIM * H_DIM / 4);

    dim3 ggrid(G_DIM / 128, T_STEPS / 128);
    gemm_xg_h<<<ggrid, 256>>>(b_ih, b_hh);

    lstm_kernel<<<NB, 256, smem>>>(W_out);

    reduce_out<<<(T_STEPS + 255) / 256, 256>>>(b_out, out);
}